// round 12
// baseline (speedup 1.0000x reference)
#include <cuda_runtime.h>
#include <cuda_fp16.h>
#include <cstdint>

// ---------------- problem constants ----------------
#define N_FEAT   131072
#define DIM      128
#define K_CENT   1024
#define M_TILE   128
#define N_CHUNK  64
#define N_CHUNKS (K_CENT / N_CHUNK)       // 16
#define N_CTAS   (N_FEAT / M_TILE)        // 1024

// ---------------- SMEM map ----------------
// [0, 32768)       A tile: 128 rows x 256B f16, chunk^row swizzle (LIVE until epilogue!)
// [32768, 98304)   B ring: 4 buffers x 16 KB; reused as epilogue scratch after mainloop
#define SM_B       32768u
#define SMEM_BYTES 98304u

// ---------------- device scratch ----------------
__device__ __half        g_ch[K_CENT * DIM];   // normalized centers, f16
__device__ float         g_partial[N_CTAS];     // per-CTA loss partials
__device__ unsigned int  g_ticket;              // last-CTA ticket (zero-init, self-reset)

// ---------------- helpers ----------------
__device__ __forceinline__ unsigned pack_h2(float lo, float hi) {
    __half2 p = __floats2half2_rn(lo, hi);
    return *reinterpret_cast<unsigned*>(&p);
}

__device__ __forceinline__ uint32_t hmax2u(uint32_t a, uint32_t b) {
    uint32_t r;
    asm("max.f16x2 %0, %1, %2;" : "=r"(r) : "r"(a), "r"(b));
    return r;
}

__device__ __forceinline__ void ldm_x4(uint32_t& r0, uint32_t& r1, uint32_t& r2,
                                       uint32_t& r3, uint32_t addr) {
    asm volatile("ldmatrix.sync.aligned.m8n8.x4.shared.b16 {%0,%1,%2,%3}, [%4];\n"
                 : "=r"(r0), "=r"(r1), "=r"(r2), "=r"(r3)
                 : "r"(addr));
}

// f16 accumulators: D/C are 2 regs; c[0] = (row lo, cols 2j,2j+1), c[1] = (row hi, same)
__device__ __forceinline__ void mma_f16(uint32_t* c,
                                        uint32_t a0, uint32_t a1, uint32_t a2, uint32_t a3,
                                        uint32_t b0, uint32_t b1) {
    asm volatile("mma.sync.aligned.m16n8k16.row.col.f16.f16.f16.f16 "
                 "{%0,%1}, {%2,%3,%4,%5}, {%6,%7}, {%0,%1};\n"
                 : "+r"(c[0]), "+r"(c[1])
                 : "r"(a0), "r"(a1), "r"(a2), "r"(a3), "r"(b0), "r"(b1));
}

__device__ __forceinline__ void cp16(uint32_t dst, const void* src) {
    asm volatile("cp.async.cg.shared.global [%0], [%1], 16;\n" :: "r"(dst), "l"(src));
}
#define CP_COMMIT() asm volatile("cp.async.commit_group;\n" ::: "memory")
#define CP_WAIT2()  asm volatile("cp.async.wait_group 2;\n" ::: "memory")

// ---------------- kernel 1: normalize centers -> f16 (warp per center) ----------------
__global__ void prep_centers(const float* __restrict__ C) {
    int w    = threadIdx.x >> 5;
    int lane = threadIdx.x & 31;
    int k    = blockIdx.x * 8 + w;
    const float4* row = reinterpret_cast<const float4*>(C + (size_t)k * DIM);
    float4 v = row[lane];
    float ss = v.x * v.x + v.y * v.y + v.z * v.z + v.w * v.w;
    #pragma unroll
    for (int off = 16; off; off >>= 1) ss += __shfl_xor_sync(0xffffffffu, ss, off);
    float inv = 1.0f / fmaxf(sqrtf(ss), 1e-12f);
    uint2 o;
    o.x = pack_h2(v.x * inv, v.y * inv);
    o.y = pack_h2(v.z * inv, v.w * inv);
    *reinterpret_cast<uint2*>(
        reinterpret_cast<unsigned char*>(g_ch) + (size_t)k * 256 + lane * 8) = o;
}

// ---------------- kernel 2: fused f16 GEMM + packed argmax + exact loss ----------------
// Warp w: M rows [32*(w&3), +32) x N cols [32*(w>>2), +32) of each 64-center chunk.
// Swizzle: 16B chunk c of row r stored at chunk (c ^ (r & 7)); rows 256B.
__global__ void __launch_bounds__(256, 2)
cluster_main(const float* __restrict__ F, const float* __restrict__ Craw,
             float* __restrict__ out) {
    extern __shared__ unsigned char smem_raw[];
    const uint32_t smem_u32 = (uint32_t)__cvta_generic_to_shared(smem_raw);

    const int t    = threadIdx.x;
    const int lane = t & 31;
    const int warp = t >> 5;
    const int mrow_base = (warp & 3) * 32;
    const int nh        = warp >> 2;            // N half (0/1)
    const int m0   = blockIdx.x * M_TILE;

    // ---- B staging addressing (thread: one center row quarter = 4 x 16B) ----
    const int bn = t >> 2;                      // center row in chunk 0..63
    const int bq = t & 3;
    uint32_t bdst[4];
    #pragma unroll
    for (int i = 0; i < 4; i++) {
        int c = bq * 4 + i;
        bdst[i] = (uint32_t)(bn * 256 + ((c ^ (bn & 7)) * 16));
    }
    const __half* bsrc0 = g_ch + (size_t)bn * DIM + bq * 32;

    // ---- prefetch B chunks 0,1,2 into ring buffers 0,1,2 ----
    #pragma unroll
    for (int n = 0; n < 3; n++) {
        uint32_t db = smem_u32 + SM_B + (uint32_t)n * 16384u;
        const __half* s = bsrc0 + (size_t)n * N_CHUNK * DIM;
        #pragma unroll
        for (int i = 0; i < 4; i++) cp16(db + bdst[i], s + i * 8);
        CP_COMMIT();
    }

    // ---- load + normalize features into swizzled f16 A SMEM [0, 32768) ----
    {
        int r = t >> 1;
        int h = t & 1;
        const float4* gp =
            reinterpret_cast<const float4*>(F + (size_t)(m0 + r) * DIM + h * 64);
        float ss = 0.f;
        #pragma unroll
        for (int i = 0; i < 16; i++) {
            float4 a = gp[i];
            ss += a.x * a.x + a.y * a.y + a.z * a.z + a.w * a.w;
        }
        ss += __shfl_xor_sync(0xffffffffu, ss, 1);   // partner lane = same row
        float inv = 1.0f / fmaxf(sqrtf(ss), 1e-12f);
        #pragma unroll
        for (int i = 0; i < 8; i++) {
            float4 a = gp[2 * i];
            float4 b = gp[2 * i + 1];
            uint4 val;
            val.x = pack_h2(a.x * inv, a.y * inv);
            val.y = pack_h2(a.z * inv, a.w * inv);
            val.z = pack_h2(b.x * inv, b.y * inv);
            val.w = pack_h2(b.z * inv, b.w * inv);
            int c = h * 8 + i;
            *reinterpret_cast<uint4*>(smem_raw + r * 256 + ((c ^ (r & 7)) * 16)) = val;
        }
    }
    __syncthreads();

    // ---- register all A fragments (2 m-tiles x 8 k-steps x 4 regs = 64) ----
    const int sub = lane >> 3, li = lane & 7;
    uint32_t af[2][8][4];
    #pragma unroll
    for (int mi = 0; mi < 2; mi++) {
        int a_row = mrow_base + 16 * mi + ((sub & 1) << 3) + li;
        uint32_t ra = smem_u32 + a_row * 256;
        int r7 = a_row & 7;
        int cadd = sub >> 1;
        #pragma unroll
        for (int ks = 0; ks < 8; ks++)
            ldm_x4(af[mi][ks][0], af[mi][ks][1], af[mi][ks][2], af[mi][ks][3],
                   ra + ((((ks << 1) + cadd) ^ r7) << 4));
    }

    // ---- B ldmatrix addressing (this warp's 32-col half: 2 groups of 16 rows) ----
    const int b_ck = sub & 1;
    uint32_t b_off[2];
    int      b_r7[2];
    #pragma unroll
    for (int jj = 0; jj < 2; jj++) {
        int nr = 32 * nh + 16 * jj + ((sub >> 1) << 3) + li;
        b_off[jj] = (uint32_t)(nr * 256);
        b_r7[jj]  = nr & 7;
    }

    // best[mi][h] = packed half2 running max (even col, odd col); indices per half
    uint32_t best[2][2] = {{0u, 0u}, {0u, 0u}};
    int      bil[2][2]  = {{0, 0}, {0, 0}};      // even-col argmax
    int      bih[2][2]  = {{1, 1}, {1, 1}};      // odd-col argmax

    // ---- main loop: 16 chunks, 4-buffer ring, prefetch distance 3, one sync/iter ----
    for (int ch = 0; ch < N_CHUNKS; ch++) {
        CP_WAIT2();
        __syncthreads();     // chunk ch ready; iter ch-1 fully consumed

        if (ch + 3 < N_CHUNKS) {
            uint32_t db = smem_u32 + SM_B + (uint32_t)((ch + 3) & 3) * 16384u;
            const __half* s = bsrc0 + (size_t)(ch + 3) * N_CHUNK * DIM;
            #pragma unroll
            for (int i = 0; i < 4; i++) cp16(db + bdst[i], s + i * 8);
        }
        CP_COMMIT();         // always: keeps wait_group(2) accounting uniform

        const uint32_t bb = smem_u32 + SM_B + (uint32_t)(ch & 3) * 16384u;
        // acc[mi][nt][h]; init +2.0 per half -> values stay positive (sims in [-1,1])
        uint32_t acc[2][4][2];
        #pragma unroll
        for (int mi = 0; mi < 2; mi++)
            #pragma unroll
            for (int nt = 0; nt < 4; nt++) {
                acc[mi][nt][0] = 0x40004000u;
                acc[mi][nt][1] = 0x40004000u;
            }

        #pragma unroll
        for (int ks = 0; ks < 8; ks++) {
            #pragma unroll
            for (int jj = 0; jj < 2; jj++) {
                uint32_t b0, b1, b2, b3;
                ldm_x4(b0, b1, b2, b3,
                       bb + b_off[jj] + ((((ks << 1) + b_ck) ^ b_r7[jj]) << 4));
                mma_f16(acc[0][2 * jj],     af[0][ks][0], af[0][ks][1], af[0][ks][2], af[0][ks][3], b0, b1);
                mma_f16(acc[0][2 * jj + 1], af[0][ks][0], af[0][ks][1], af[0][ks][2], af[0][ks][3], b2, b3);
                mma_f16(acc[1][2 * jj],     af[1][ks][0], af[1][ks][1], af[1][ks][2], af[1][ks][3], b0, b1);
                mma_f16(acc[1][2 * jj + 1], af[1][ks][0], af[1][ks][1], af[1][ks][2], af[1][ks][3], b2, b3);
            }
        }

        // packed running argmax: positive f16 -> per-half numeric max; index search only on improvement
        const int cb = ch * N_CHUNK + 32 * nh + 2 * (lane & 3);
        #pragma unroll
        for (int mi = 0; mi < 2; mi++) {
            #pragma unroll
            for (int h = 0; h < 2; h++) {
                uint32_t cur = hmax2u(hmax2u(acc[mi][0][h], acc[mi][1][h]),
                                      hmax2u(acc[mi][2][h], acc[mi][3][h]));
                uint32_t nb = hmax2u(best[mi][h], cur);
                if (nb != best[mi][h]) {
                    uint32_t lo = nb & 0xFFFFu;
                    if (lo != (best[mi][h] & 0xFFFFu)) {
                        if      ((acc[mi][0][h] & 0xFFFFu) == lo) bil[mi][h] = cb;
                        else if ((acc[mi][1][h] & 0xFFFFu) == lo) bil[mi][h] = cb + 8;
                        else if ((acc[mi][2][h] & 0xFFFFu) == lo) bil[mi][h] = cb + 16;
                        else                                      bil[mi][h] = cb + 24;
                    }
                    uint32_t hi = nb >> 16;
                    if (hi != (best[mi][h] >> 16)) {
                        if      ((acc[mi][0][h] >> 16) == hi) bih[mi][h] = cb + 1;
                        else if ((acc[mi][1][h] >> 16) == hi) bih[mi][h] = cb + 9;
                        else if ((acc[mi][2][h] >> 16) == hi) bih[mi][h] = cb + 17;
                        else                                  bih[mi][h] = cb + 25;
                    }
                    best[mi][h] = nb;
                }
            }
        }
    }

    // ---- build comparable keys: (f16 value << 16) | (1023 - idx); reduce over quad ----
    int key[2][2];
    #pragma unroll
    for (int mi = 0; mi < 2; mi++) {
        #pragma unroll
        for (int h = 0; h < 2; h++) {
            int kA = (int)(((best[mi][h] & 0xFFFFu) << 16) | (uint32_t)(1023 - bil[mi][h]));
            int kB = (int)(((best[mi][h] >> 16) << 16)     | (uint32_t)(1023 - bih[mi][h]));
            int k  = max(kA, kB);
            #pragma unroll
            for (int off = 1; off <= 2; off <<= 1)
                k = max(k, __shfl_xor_sync(0xffffffffu, k, off));
            key[mi][h] = k;
        }
    }

    // ---- publish per-row keys (B ring is dead; A tile stays LIVE) ----
    __syncthreads();
    int* ks_sm = reinterpret_cast<int*>(smem_raw + SM_B);     // [2][128]
    if ((lane & 3) == 0) {
        int r0 = mrow_base + (lane >> 2);
        #pragma unroll
        for (int mi = 0; mi < 2; mi++)
            #pragma unroll
            for (int h = 0; h < 2; h++)
                ks_sm[nh * 128 + (r0 + 16 * mi + 8 * h)] = key[mi][h];
    }
    __syncthreads();

    // ---- exact per-row loss: sum (f16_feat - C_fp32)^2, C from global ----
    float* lr = reinterpret_cast<float*>(smem_raw + SM_B + 2048);  // [128]
    if (t < 128) {
        int k   = max(ks_sm[t], ks_sm[128 + t]);
        int idx = 1023 - (k & 0x3FF);
        const float4* cp = reinterpret_cast<const float4*>(Craw + (size_t)idx * DIM);
        float lsum = 0.f;
        #pragma unroll
        for (int j = 0; j < 16; j++) {
            uint4 fb = *reinterpret_cast<const uint4*>(
                smem_raw + (uint32_t)(t * 256 + ((j ^ (t & 7)) * 16)));
            float4 c0 = cp[2 * j], c1 = cp[2 * j + 1];
            float2 f0 = __half22float2(*reinterpret_cast<__half2*>(&fb.x));
            float2 f1 = __half22float2(*reinterpret_cast<__half2*>(&fb.y));
            float2 f2 = __half22float2(*reinterpret_cast<__half2*>(&fb.z));
            float2 f3 = __half22float2(*reinterpret_cast<__half2*>(&fb.w));
            float d;
            d = f0.x - c0.x; lsum += d * d;
            d = f0.y - c0.y; lsum += d * d;
            d = f1.x - c0.z; lsum += d * d;
            d = f1.y - c0.w; lsum += d * d;
            d = f2.x - c1.x; lsum += d * d;
            d = f2.y - c1.y; lsum += d * d;
            d = f3.x - c1.z; lsum += d * d;
            d = f3.y - c1.w; lsum += d * d;
        }
        lr[t] = lsum;
    }
    __syncthreads();
    #pragma unroll
    for (int off = 64; off; off >>= 1) {
        if (t < off) lr[t] += lr[t + off];
        __syncthreads();
    }

    // ---- publish partial + last-CTA fused final reduce ----
    int* sflag = reinterpret_cast<int*>(smem_raw + SM_B + 3072);
    if (t == 0) {
        g_partial[blockIdx.x] = lr[0];
        __threadfence();
        unsigned v = atomicAdd(&g_ticket, 1u);
        *sflag = (v == N_CTAS - 1);
    }
    __syncthreads();
    if (*sflag) {
        __threadfence();                        // acquire all partials
        float* sh = reinterpret_cast<float*>(smem_raw + SM_B + 4096);
        float s = __ldcg(&g_partial[t])       + __ldcg(&g_partial[t + 256])
                + __ldcg(&g_partial[t + 512]) + __ldcg(&g_partial[t + 768]);
        sh[t] = s;
        __syncthreads();
        #pragma unroll
        for (int off = 128; off; off >>= 1) {
            if (t < off) sh[t] += sh[t + off];
            __syncthreads();
        }
        if (t == 0) {
            out[0] = sh[0] / (float)N_FEAT;
            g_ticket = 0;                       // reset for next graph replay
        }
    }
}

// ---------------- launch ----------------
extern "C" void kernel_launch(void* const* d_in, const int* in_sizes, int n_in,
                              void* d_out, int out_size) {
    const float* features = (const float*)d_in[0];
    const float* centers  = (const float*)d_in[1];
    if (n_in >= 2 && in_sizes[0] < in_sizes[1]) {   // defensive: order by size
        const float* tmp = features; features = centers; centers = tmp;
    }
    cudaFuncSetAttribute(cluster_main,
                         cudaFuncAttributeMaxDynamicSharedMemorySize, SMEM_BYTES);
    prep_centers<<<K_CENT / 8, 256>>>(centers);
    cluster_main<<<N_CTAS, 256, SMEM_BYTES>>>(features, centers, (float*)d_out);
}

// round 14
// speedup vs baseline: 1.4196x; 1.4196x over previous
#include <cuda_runtime.h>
#include <cuda_bf16.h>
#include <cstdint>

// ---------------- problem constants ----------------
#define N_FEAT   131072
#define DIM      128
#define K_CENT   1024
#define M_TILE   128
#define N_CHUNK  64
#define N_CHUNKS (K_CENT / N_CHUNK)       // 16
#define N_CTAS   (N_FEAT / M_TILE)        // 1024

// ---------------- SMEM map ----------------
// [0, 32768)       A tile: 128 rows x 256B bf16, chunk^row swizzle
// [32768, 98304)   B ring: 4 buffers x 16 KB (64 rows x 256B each)
#define SM_B       32768u
#define SMEM_BYTES 98304u

// ---------------- device scratch ----------------
__device__ __nv_bfloat16 g_cbf[K_CENT * DIM];  // normalized centers, bf16
__device__ float         g_cn1[K_CENT];         // ||C_k||
__device__ float         g_cn2[K_CENT];         // ||C_k||^2
__device__ float         g_partial[N_CTAS];     // per-CTA loss partials
__device__ unsigned int  g_ticket;              // last-CTA ticket (zero-init, self-reset)

// ---------------- helpers ----------------
__device__ __forceinline__ unsigned pack_bf16x2(float lo, float hi) {
    __nv_bfloat162 p = __floats2bfloat162_rn(lo, hi);
    return *reinterpret_cast<unsigned*>(&p);
}

__device__ __forceinline__ void ldm_x4(uint32_t& r0, uint32_t& r1, uint32_t& r2,
                                       uint32_t& r3, uint32_t addr) {
    asm volatile("ldmatrix.sync.aligned.m8n8.x4.shared.b16 {%0,%1,%2,%3}, [%4];\n"
                 : "=r"(r0), "=r"(r1), "=r"(r2), "=r"(r3)
                 : "r"(addr));
}

__device__ __forceinline__ void mma_bf16(float* c,
                                         uint32_t a0, uint32_t a1, uint32_t a2, uint32_t a3,
                                         uint32_t b0, uint32_t b1) {
    asm volatile("mma.sync.aligned.m16n8k16.row.col.f32.bf16.bf16.f32 "
                 "{%0,%1,%2,%3}, {%4,%5,%6,%7}, {%8,%9}, {%0,%1,%2,%3};\n"
                 : "+f"(c[0]), "+f"(c[1]), "+f"(c[2]), "+f"(c[3])
                 : "r"(a0), "r"(a1), "r"(a2), "r"(a3), "r"(b0), "r"(b1));
}

__device__ __forceinline__ void cp16(uint32_t dst, const void* src) {
    asm volatile("cp.async.cg.shared.global [%0], [%1], 16;\n" :: "r"(dst), "l"(src));
}
#define CP_COMMIT() asm volatile("cp.async.commit_group;\n" ::: "memory")
#define CP_WAIT2()  asm volatile("cp.async.wait_group 2;\n" ::: "memory")

// packed argmax key: (fp32 bits of (2+sim) with low 10 bits cleared) | (1023 - idx)
__device__ __forceinline__ int mkkey(float a, int idxfield) {
    return (int)((__float_as_uint(a) & 0xFFFFFC00u) | (uint32_t)idxfield);
}

// ---------------- kernel 1: normalize centers (warp per center) ----------------
__global__ void prep_centers(const float* __restrict__ C) {
    int w    = threadIdx.x >> 5;
    int lane = threadIdx.x & 31;
    int k    = blockIdx.x * 8 + w;
    const float4* row = reinterpret_cast<const float4*>(C + (size_t)k * DIM);
    float4 v = row[lane];
    float ss = v.x * v.x + v.y * v.y + v.z * v.z + v.w * v.w;
    #pragma unroll
    for (int off = 16; off; off >>= 1) ss += __shfl_xor_sync(0xffffffffu, ss, off);
    float norm = sqrtf(ss);
    float inv  = 1.0f / fmaxf(norm, 1e-12f);
    uint2 o;
    o.x = pack_bf16x2(v.x * inv, v.y * inv);
    o.y = pack_bf16x2(v.z * inv, v.w * inv);
    *reinterpret_cast<uint2*>(
        reinterpret_cast<unsigned char*>(g_cbf) + (size_t)k * 256 + lane * 8) = o;
    if (lane == 0) { g_cn1[k] = norm; g_cn2[k] = ss; }
}

// ---------------- kernel 2: fused GEMM + packed argmax + loss + final reduce ----------------
// Warp w: M rows [32*(w&3), +32) x N cols [32*(w>>2), +32) of each 64-center chunk.
// Swizzle: 16B chunk c of row r stored at chunk (c ^ (r & 7)); rows 256B.
__global__ void __launch_bounds__(256, 2)
cluster_main(const float* __restrict__ F, float* __restrict__ out) {
    extern __shared__ unsigned char smem_raw[];
    const uint32_t smem_u32 = (uint32_t)__cvta_generic_to_shared(smem_raw);

    const int t    = threadIdx.x;
    const int lane = t & 31;
    const int warp = t >> 5;
    const int mrow_base = (warp & 3) * 32;
    const int nh        = warp >> 2;            // N half (0/1)
    const int m0   = blockIdx.x * M_TILE;

    // ---- B staging addressing (thread: one center row quarter = 4 x 16B) ----
    const int bn = t >> 2;                      // center row in chunk 0..63
    const int bq = t & 3;
    uint32_t bdst[4];
    #pragma unroll
    for (int i = 0; i < 4; i++) {
        int c = bq * 4 + i;
        bdst[i] = (uint32_t)(bn * 256 + ((c ^ (bn & 7)) * 16));
    }
    const __nv_bfloat16* bsrc0 = g_cbf + (size_t)bn * DIM + bq * 32;

    // ---- prefetch B chunks 0,1,2 into ring buffers 0,1,2 ----
    #pragma unroll
    for (int n = 0; n < 3; n++) {
        uint32_t db = smem_u32 + SM_B + (uint32_t)n * 16384u;
        const __nv_bfloat16* s = bsrc0 + (size_t)n * N_CHUNK * DIM;
        #pragma unroll
        for (int i = 0; i < 4; i++) cp16(db + bdst[i], s + i * 8);
        CP_COMMIT();
    }

    // ---- load + normalize features into swizzled bf16 A SMEM [0, 32768) ----
    {
        int r = t >> 1;
        int h = t & 1;
        const float4* gp =
            reinterpret_cast<const float4*>(F + (size_t)(m0 + r) * DIM + h * 64);
        float ss = 0.f;
        #pragma unroll
        for (int i = 0; i < 16; i++) {
            float4 a = gp[i];
            ss += a.x * a.x + a.y * a.y + a.z * a.z + a.w * a.w;
        }
        ss += __shfl_xor_sync(0xffffffffu, ss, 1);   // partner lane = same row
        float inv = 1.0f / fmaxf(sqrtf(ss), 1e-12f);
        #pragma unroll
        for (int i = 0; i < 8; i++) {
            float4 a = gp[2 * i];
            float4 b = gp[2 * i + 1];
            uint4 val;
            val.x = pack_bf16x2(a.x * inv, a.y * inv);
            val.y = pack_bf16x2(a.z * inv, a.w * inv);
            val.z = pack_bf16x2(b.x * inv, b.y * inv);
            val.w = pack_bf16x2(b.z * inv, b.w * inv);
            int c = h * 8 + i;
            *reinterpret_cast<uint4*>(smem_raw + r * 256 + ((c ^ (r & 7)) * 16)) = val;
        }
    }
    __syncthreads();

    // ---- register all A fragments (2 m-tiles x 8 k-steps x 4 regs = 64) ----
    const int sub = lane >> 3, li = lane & 7;
    uint32_t af[2][8][4];
    #pragma unroll
    for (int mi = 0; mi < 2; mi++) {
        int a_row = mrow_base + 16 * mi + ((sub & 1) << 3) + li;
        uint32_t ra = smem_u32 + a_row * 256;
        int r7 = a_row & 7;
        int cadd = sub >> 1;
        #pragma unroll
        for (int ks = 0; ks < 8; ks++)
            ldm_x4(af[mi][ks][0], af[mi][ks][1], af[mi][ks][2], af[mi][ks][3],
                   ra + ((((ks << 1) + cadd) ^ r7) << 4));
    }

    // ---- B ldmatrix addressing (this warp's 32-col half: 2 groups of 16 rows) ----
    const int b_ck = sub & 1;
    uint32_t b_off[2];
    int      b_r7[2];
    #pragma unroll
    for (int jj = 0; jj < 2; jj++) {
        int nr = 32 * nh + 16 * jj + ((sub >> 1) << 3) + li;
        b_off[jj] = (uint32_t)(nr * 256);
        b_r7[jj]  = nr & 7;
    }

    // running packed-key argmax; bestk[mi][h] covers row (mrow_base+16mi+8h+(lane>>2))
    int bestk[2][2] = {{0, 0}, {0, 0}};         // value>=1 -> key > 0 always wins init

    // ---- main loop: 16 chunks, 4-buffer ring, prefetch distance 3, one sync/iter ----
    for (int ch = 0; ch < N_CHUNKS; ch++) {
        CP_WAIT2();
        __syncthreads();     // chunk ch ready; iter ch-1 fully consumed

        // prefetch ch+3 into buffer (ch+3)&3 (consumed at iter ch-1 -> safe)
        if (ch + 3 < N_CHUNKS) {
            uint32_t db = smem_u32 + SM_B + (uint32_t)((ch + 3) & 3) * 16384u;
            const __nv_bfloat16* s = bsrc0 + (size_t)(ch + 3) * N_CHUNK * DIM;
            #pragma unroll
            for (int i = 0; i < 4; i++) cp16(db + bdst[i], s + i * 8);
        }
        CP_COMMIT();         // always: keeps wait_group(2) accounting uniform

        const uint32_t bb = smem_u32 + SM_B + (uint32_t)(ch & 3) * 16384u;
        // acc init +2.0f: sims in [-1,1] -> final in [1,3], positive -> int-comparable bits
        float acc[2][4][4];
        #pragma unroll
        for (int mi = 0; mi < 2; mi++)
            #pragma unroll
            for (int nt = 0; nt < 4; nt++)
                #pragma unroll
                for (int v = 0; v < 4; v++) acc[mi][nt][v] = 2.0f;

        #pragma unroll
        for (int ks = 0; ks < 8; ks++) {
            #pragma unroll
            for (int jj = 0; jj < 2; jj++) {
                uint32_t b0, b1, b2, b3;
                ldm_x4(b0, b1, b2, b3,
                       bb + b_off[jj] + ((((ks << 1) + b_ck) ^ b_r7[jj]) << 4));
                mma_bf16(acc[0][2 * jj],     af[0][ks][0], af[0][ks][1], af[0][ks][2], af[0][ks][3], b0, b1);
                mma_bf16(acc[0][2 * jj + 1], af[0][ks][0], af[0][ks][1], af[0][ks][2], af[0][ks][3], b2, b3);
                mma_bf16(acc[1][2 * jj],     af[1][ks][0], af[1][ks][1], af[1][ks][2], af[1][ks][3], b0, b1);
                mma_bf16(acc[1][2 * jj + 1], af[1][ks][0], af[1][ks][1], af[1][ks][2], af[1][ks][3], b2, b3);
            }
        }

        // branch-free packed argmax: 1 LOP3 + 1 IMNMX per sim, lat-4 chains
        const int idx0 = 1023 - (ch * N_CHUNK + 32 * nh + 2 * (lane & 3));
        #pragma unroll
        for (int mi = 0; mi < 2; mi++) {
            #pragma unroll
            for (int nt = 0; nt < 4; nt++) {
                const int fi = idx0 - 8 * nt;   // field for even col; odd col = fi-1
                float* a4 = acc[mi][nt];
                bestk[mi][0] = max(bestk[mi][0], mkkey(a4[0], fi));
                bestk[mi][0] = max(bestk[mi][0], mkkey(a4[1], fi - 1));
                bestk[mi][1] = max(bestk[mi][1], mkkey(a4[2], fi));
                bestk[mi][1] = max(bestk[mi][1], mkkey(a4[3], fi - 1));
            }
        }
    }

    // ---- quad reduce keys across the 4 lanes sharing each row ----
    #pragma unroll
    for (int off = 1; off <= 2; off <<= 1) {
        #pragma unroll
        for (int mi = 0; mi < 2; mi++)
            #pragma unroll
            for (int h = 0; h < 2; h++)
                bestk[mi][h] = max(bestk[mi][h],
                                   __shfl_xor_sync(0xffffffffu, bestk[mi][h], off));
    }

    // ---- combine the two N-half warps per row (A region dead; reuse) ----
    __syncthreads();
    int* ks_sm = reinterpret_cast<int*>(smem_raw);            // [2][128]
    if ((lane & 3) == 0) {
        int r0 = mrow_base + (lane >> 2);
        #pragma unroll
        for (int mi = 0; mi < 2; mi++)
            #pragma unroll
            for (int h = 0; h < 2; h++)
                ks_sm[nh * 128 + (r0 + 16 * mi + 8 * h)] = bestk[mi][h];
    }
    __syncthreads();

    float* lr = reinterpret_cast<float*>(smem_raw + 2048);    // [128]
    if (t < 128) {
        int k   = max(ks_sm[t], ks_sm[128 + t]);
        int idx = 1023 - (k & 0x3FF);
        float v = __uint_as_float((uint32_t)k & 0xFFFFFC00u) - 2.0f;   // sim
        // loss row = 1 - 2 * sim * ||C|| + ||C||^2   (||f_hat||^2 = 1)
        lr[t] = 1.0f - 2.0f * v * g_cn1[idx] + g_cn2[idx];
    }
    __syncthreads();
    #pragma unroll
    for (int off = 64; off; off >>= 1) {
        if (t < off) lr[t] += lr[t + off];
        __syncthreads();
    }

    // ---- publish partial + last-CTA fused final reduce ----
    int* sflag = reinterpret_cast<int*>(smem_raw + 2560);
    if (t == 0) {
        g_partial[blockIdx.x] = lr[0];
        __threadfence();
        unsigned v = atomicAdd(&g_ticket, 1u);
        *sflag = (v == N_CTAS - 1);
    }
    __syncthreads();
    if (*sflag) {
        __threadfence();                        // acquire all partials
        float* sh = reinterpret_cast<float*>(smem_raw + 4096);
        float s = __ldcg(&g_partial[t])       + __ldcg(&g_partial[t + 256])
                + __ldcg(&g_partial[t + 512]) + __ldcg(&g_partial[t + 768]);
        sh[t] = s;
        __syncthreads();
        #pragma unroll
        for (int off = 128; off; off >>= 1) {
            if (t < off) sh[t] += sh[t + off];
            __syncthreads();
        }
        if (t == 0) {
            out[0] = sh[0] / (float)N_FEAT;
            g_ticket = 0;                       // reset for next graph replay
        }
    }
}

// ---------------- launch ----------------
extern "C" void kernel_launch(void* const* d_in, const int* in_sizes, int n_in,
                              void* d_out, int out_size) {
    const float* features = (const float*)d_in[0];
    const float* centers  = (const float*)d_in[1];
    if (n_in >= 2 && in_sizes[0] < in_sizes[1]) {   // defensive: order by size
        const float* tmp = features; features = centers; centers = tmp;
    }
    cudaFuncSetAttribute(cluster_main,
                         cudaFuncAttributeMaxDynamicSharedMemorySize, SMEM_BYTES);
    prep_centers<<<K_CENT / 8, 256>>>(centers);
    cluster_main<<<N_CTAS, 256, SMEM_BYTES>>>(features, (float*)d_out);
}